// round 2
// baseline (speedup 1.0000x reference)
#include <cuda_runtime.h>
#include <math.h>

#define Bz 2
#define Ssz 2048
#define Ez 768
#define Hh 12
#define Dd 64
#define FFN 3072
#define Mz (Bz*Ssz)          // 4096
#define WIN 64

// ---------------- scratch (static device arrays; no allocation) -------------
__device__ float g_Q[Mz*Ez];
__device__ float g_K[Mz*Ez];
__device__ float g_V[Mz*Ez];
__device__ float g_ctx[Mz*Ez];
__device__ float g_t1[Mz*Ez];
__device__ float g_h[Mz*Ez];
__device__ float g_gate[(size_t)Mz*FFN];

// ---------------- GEMM: C[m][n] = sum_k A[m][k]*W[n][k] + bias[n] -----------
// EPI: 0 plain | 1 += R | 2 gelu(exact) | 3 *= R
#define BM 64
#define BN 64
#define BK 16

template<int EPI>
__global__ void gemm_bias(const float* __restrict__ A, const float* __restrict__ W,
                          const float* __restrict__ bias, const float* __restrict__ R,
                          float* __restrict__ C, int M, int N, int K)
{
    __shared__ float As[BK][BM];
    __shared__ float Ws[BK][BN];
    const int tx = threadIdx.x, ty = threadIdx.y;      // 16 x 16
    const int tid = ty * 16 + tx;
    const int bm = blockIdx.y * BM, bn = blockIdx.x * BN;

    float acc[4][4] = {};

    const int lr = tid >> 2;          // 0..63: row within tile
    const int lc = (tid & 3) * 4;     // 0,4,8,12: k offset

    for (int kb = 0; kb < K; kb += BK) {
        float4 a = *(const float4*)&A[(size_t)(bm + lr) * K + kb + lc];
        As[lc + 0][lr] = a.x; As[lc + 1][lr] = a.y;
        As[lc + 2][lr] = a.z; As[lc + 3][lr] = a.w;
        float4 w = *(const float4*)&W[(size_t)(bn + lr) * K + kb + lc];
        Ws[lc + 0][lr] = w.x; Ws[lc + 1][lr] = w.y;
        Ws[lc + 2][lr] = w.z; Ws[lc + 3][lr] = w.w;
        __syncthreads();
        #pragma unroll
        for (int k = 0; k < BK; k++) {
            float4 av = *(const float4*)&As[k][ty * 4];
            float4 wv = *(const float4*)&Ws[k][tx * 4];
            float aa[4] = {av.x, av.y, av.z, av.w};
            float ww[4] = {wv.x, wv.y, wv.z, wv.w};
            #pragma unroll
            for (int i = 0; i < 4; i++)
                #pragma unroll
                for (int j = 0; j < 4; j++)
                    acc[i][j] += aa[i] * ww[j];
        }
        __syncthreads();
    }

    #pragma unroll
    for (int i = 0; i < 4; i++) {
        int m = bm + ty * 4 + i;
        #pragma unroll
        for (int j = 0; j < 4; j++) {
            int n = bn + tx * 4 + j;
            float c = acc[i][j] + bias[n];
            if (EPI == 1) c += R[(size_t)m * N + n];
            if (EPI == 2) c = 0.5f * c * (1.0f + erff(c * 0.70710678118654752f));
            if (EPI == 3) c *= R[(size_t)m * N + n];
            C[(size_t)m * N + n] = c;
        }
    }
}

// ---------------- RoPE (interleaved pairs, theta=10000), in-place -----------
__global__ void rope_kernel(float* __restrict__ X)
{
    int idx = blockIdx.x * blockDim.x + threadIdx.x;   // over Mz*Ez/2 pairs
    if (idx >= Mz * Ez / 2) return;
    int row = idx / (Ez / 2);
    int p   = idx % (Ez / 2);
    int s   = row % Ssz;
    int h   = p / (Dd / 2);
    int d2  = p % (Dd / 2);                            // pair index 0..31
    float inv = powf(10000.0f, -(float)(2 * d2) / (float)Dd);
    float fr  = (float)s * inv;
    float c = cosf(fr), sn = sinf(fr);
    float* x = X + (size_t)row * Ez + h * Dd + d2 * 2;
    float x0 = x[0], x1 = x[1];
    x[0] = x0 * c - x1 * sn;
    x[1] = x1 * c + x0 * sn;
}

// ---------------- sparse attention: block per (b,h,q) -----------------------
__global__ void attn_kernel(const float* __restrict__ Q, const float* __restrict__ K,
                            const float* __restrict__ V, const float* __restrict__ rpb,
                            const float* __restrict__ pc, float* __restrict__ ctx)
{
    __shared__ float sc[Ssz];
    __shared__ float qs[Dd];
    __shared__ float red[128];

    const int q = blockIdx.x, h = blockIdx.y, b = blockIdx.z;
    const int t = threadIdx.x;                         // 128 threads

    const float* qrow = Q + ((size_t)(b * Ssz + q)) * Ez + h * Dd;
    if (t < Dd) qs[t] = qrow[t];

    int lo = q - WIN; if (lo < 0) lo = 0;
    int hi = q + WIN; if (hi > Ssz - 1) hi = Ssz - 1;
    int extra = 0, nk;
    if (q == 0) { nk = Ssz; }
    else { extra = (lo > 0) ? 1 : 0; nk = hi - lo + 1 + extra; }
    __syncthreads();

    const float pch = pc[h];
    const float* rb = rpb + ((size_t)b * Ssz + q) * Ssz;

    for (int i = t; i < nk; i += 128) {
        int k = (q == 0) ? i : ((extra && i == 0) ? 0 : lo + i - extra);
        const float* kr = K + ((size_t)(b * Ssz + k)) * Ez + h * Dd;
        float s = 0.0f;
        #pragma unroll
        for (int d = 0; d < Dd; d++) s += qs[d] * kr[d];
        sc[i] = s * 0.125f + pch * rb[k];
    }
    __syncthreads();

    // block max
    float mx = -1e30f;
    for (int i = t; i < nk; i += 128) mx = fmaxf(mx, sc[i]);
    red[t] = mx; __syncthreads();
    for (int o = 64; o > 0; o >>= 1) { if (t < o) red[t] = fmaxf(red[t], red[t + o]); __syncthreads(); }
    mx = red[0]; __syncthreads();

    // exp + sum
    float sm = 0.0f;
    for (int i = t; i < nk; i += 128) { float e = expf(sc[i] - mx); sc[i] = e; sm += e; }
    red[t] = sm; __syncthreads();
    for (int o = 64; o > 0; o >>= 1) { if (t < o) red[t] += red[t + o]; __syncthreads(); }
    const float inv = 1.0f / red[0];
    __syncthreads();

    // ctx: 2 partial accumulators per d
    const int d = t & 63, half = t >> 6;
    float acc = 0.0f;
    for (int i = half; i < nk; i += 2) {
        int k = (q == 0) ? i : ((extra && i == 0) ? 0 : lo + i - extra);
        acc += sc[i] * V[((size_t)(b * Ssz + k)) * Ez + h * Dd + d];
    }
    red[t] = acc; __syncthreads();
    if (t < 64)
        ctx[((size_t)(b * Ssz + q)) * Ez + h * Dd + t] = (red[t] + red[t + 64]) * inv;
}

// ---------------- LayerNorm: block per row ----------------------------------
__global__ void layernorm_kernel(const float* __restrict__ X, const float* __restrict__ sc,
                                 const float* __restrict__ bi, float* __restrict__ out)
{
    __shared__ float b1[256], b2[256];
    const int row = blockIdx.x;
    const int t = threadIdx.x;                         // 256
    const float* x = X + (size_t)row * Ez;
    float sm = 0.0f, sq = 0.0f;
    for (int i = t; i < Ez; i += 256) { float v = x[i]; sm += v; sq += v * v; }
    b1[t] = sm; b2[t] = sq; __syncthreads();
    for (int o = 128; o > 0; o >>= 1) {
        if (t < o) { b1[t] += b1[t + o]; b2[t] += b2[t + o]; }
        __syncthreads();
    }
    const float mean = b1[0] * (1.0f / Ez);
    const float var  = b2[0] * (1.0f / Ez) - mean * mean;
    const float rstd = rsqrtf(var + 1e-5f);
    float* o = out + (size_t)row * Ez;
    for (int i = t; i < Ez; i += 256)
        o[i] = (x[i] - mean) * rstd * sc[i] + bi[i];
}

// ---------------- launch -----------------------------------------------------
extern "C" void kernel_launch(void* const* d_in, const int* in_sizes, int n_in,
                              void* d_out, int out_size)
{
    const float* x      = (const float*)d_in[0];
    const float* rpb    = (const float*)d_in[1];
    // d_in[2]: mask — all-True by construction, pattern handled analytically
    const float* wq_w   = (const float*)d_in[3];
    const float* wq_b   = (const float*)d_in[4];
    const float* wk_w   = (const float*)d_in[5];
    const float* wk_b   = (const float*)d_in[6];
    const float* wv_w   = (const float*)d_in[7];
    const float* wv_b   = (const float*)d_in[8];
    const float* fc_w   = (const float*)d_in[9];
    const float* fc_b   = (const float*)d_in[10];
    const float* pos    = (const float*)d_in[11];
    const float* gate_w = (const float*)d_in[12];
    const float* gate_b = (const float*)d_in[13];
    const float* val_w  = (const float*)d_in[14];
    const float* val_b  = (const float*)d_in[15];
    const float* down_w = (const float*)d_in[16];
    const float* down_b = (const float*)d_in[17];
    const float* ln1_s  = (const float*)d_in[18];
    const float* ln1_b  = (const float*)d_in[19];
    const float* ln2_s  = (const float*)d_in[20];
    const float* ln2_b  = (const float*)d_in[21];
    float* out = (float*)d_out;

    float *Q, *K, *V, *ctx, *t1, *h, *gate;
    cudaGetSymbolAddress((void**)&Q,   g_Q);
    cudaGetSymbolAddress((void**)&K,   g_K);
    cudaGetSymbolAddress((void**)&V,   g_V);
    cudaGetSymbolAddress((void**)&ctx, g_ctx);
    cudaGetSymbolAddress((void**)&t1,  g_t1);
    cudaGetSymbolAddress((void**)&h,   g_h);
    cudaGetSymbolAddress((void**)&gate, g_gate);

    dim3 blk(16, 16);
    dim3 gE(Ez / BN, Mz / BM);        // (12, 64)
    dim3 gF(FFN / BN, Mz / BM);       // (48, 64)

    // QKV projections
    gemm_bias<0><<<gE, blk>>>(x, wq_w, wq_b, nullptr, Q, Mz, Ez, Ez);
    gemm_bias<0><<<gE, blk>>>(x, wk_w, wk_b, nullptr, K, Mz, Ez, Ez);
    gemm_bias<0><<<gE, blk>>>(x, wv_w, wv_b, nullptr, V, Mz, Ez, Ez);

    // RoPE on Q, K
    int npair = Mz * Ez / 2;
    rope_kernel<<<(npair + 255) / 256, 256>>>(Q);
    rope_kernel<<<(npair + 255) / 256, 256>>>(K);

    // sparse attention
    attn_kernel<<<dim3(Ssz, Hh, Bz), 128>>>(Q, K, V, rpb, pos, ctx);

    // fc + residual, LN1
    gemm_bias<1><<<gE, blk>>>(ctx, fc_w, fc_b, x, t1, Mz, Ez, Ez);
    layernorm_kernel<<<Mz, 256>>>(t1, ln1_s, ln1_b, h);

    // GeGLU FFN: gate (gelu), value (* gate), down (+h), LN2
    gemm_bias<2><<<gF, blk>>>(h, gate_w, gate_b, nullptr, gate, Mz, FFN, Ez);
    gemm_bias<3><<<gF, blk>>>(h, val_w,  val_b,  gate,    gate, Mz, FFN, Ez);
    gemm_bias<1><<<gE, blk>>>(gate, down_w, down_b, h, t1, Mz, Ez, FFN);
    layernorm_kernel<<<Mz, 256>>>(t1, ln2_s, ln2_b, out);
}

// round 3
// speedup vs baseline: 1.6668x; 1.6668x over previous
#include <cuda_runtime.h>
#include <math.h>
#include <stdint.h>

#define Bz 2
#define Ssz 2048
#define Ez 768
#define Hh 12
#define Dd 64
#define FFN 3072
#define Mz (Bz*Ssz)          // 4096
#define WIN 64

// ---------------- scratch (static device arrays; no allocation) -------------
__device__ float g_Q[Mz*Ez];
__device__ float g_K[Mz*Ez];
__device__ float g_V[Mz*Ez];
__device__ float g_ctx[Mz*Ez];
__device__ float g_t1[Mz*Ez];
__device__ float g_h[Mz*Ez];
__device__ float g_gate[(size_t)Mz*FFN];

// ---------------- tf32 tensor-core GEMM -------------------------------------
// C[m][n] = sum_k A[m][k]*W[n][k] + bias[n]
// EPI: 0 plain | 1 += R | 2 gelu(exact) | 3 *= R
// Block tile 128x128, BK=16, 256 threads = 8 warps (2x4), warp tile 64x32.

__device__ __forceinline__ uint32_t f2tf32(float f) {
    uint32_t u;
    asm("cvt.rna.tf32.f32 %0, %1;" : "=r"(u) : "f"(f));
    return u;
}

__device__ __forceinline__ void mma_tf32(float c[4], const uint32_t a[4], const uint32_t b[2]) {
    asm volatile(
        "mma.sync.aligned.m16n8k8.row.col.f32.tf32.tf32.f32 "
        "{%0,%1,%2,%3}, {%4,%5,%6,%7}, {%8,%9}, {%0,%1,%2,%3};\n"
        : "+f"(c[0]), "+f"(c[1]), "+f"(c[2]), "+f"(c[3])
        : "r"(a[0]), "r"(a[1]), "r"(a[2]), "r"(a[3]), "r"(b[0]), "r"(b[1]));
}

#define GBK 16
#define SMS 20   // smem row stride (words), padded: conflict-free fragment loads

template<int EPI>
__global__ void __launch_bounds__(256, 2)
gemm_tf32(const float* __restrict__ A, const float* __restrict__ W,
          const float* __restrict__ bias, const float* __restrict__ R,
          float* __restrict__ C, int M, int N, int K)
{
    __shared__ uint32_t As[128][SMS];
    __shared__ uint32_t Ws[128][SMS];

    const int tid  = threadIdx.x;
    const int lane = tid & 31;
    const int warp = tid >> 5;
    const int wm = warp >> 2;            // 0..1
    const int wn = warp & 3;             // 0..3
    const int gr = lane >> 2;            // groupID 0..7
    const int gc = lane & 3;             // threadID_in_group 0..3
    const int bm = blockIdx.y * 128, bn = blockIdx.x * 128;

    // global-load mapping: 512 float4 per tile, 2 per thread
    const int r0 = tid >> 2;             // rows 0..63   (idx = tid)
    const int r1 = r0 + 64;              // rows 64..127 (idx = tid+256)
    const int c4 = (tid & 3) * 4;        // k offset 0,4,8,12

    float acc[4][4][4] = {};
    float4 pa0, pa1, pw0, pw1;

    // prologue: load tile kb=0
    pa0 = *(const float4*)&A[(size_t)(bm + r0) * K + c4];
    pa1 = *(const float4*)&A[(size_t)(bm + r1) * K + c4];
    pw0 = *(const float4*)&W[(size_t)(bn + r0) * K + c4];
    pw1 = *(const float4*)&W[(size_t)(bn + r1) * K + c4];
    {
        As[r0][c4+0]=f2tf32(pa0.x); As[r0][c4+1]=f2tf32(pa0.y); As[r0][c4+2]=f2tf32(pa0.z); As[r0][c4+3]=f2tf32(pa0.w);
        As[r1][c4+0]=f2tf32(pa1.x); As[r1][c4+1]=f2tf32(pa1.y); As[r1][c4+2]=f2tf32(pa1.z); As[r1][c4+3]=f2tf32(pa1.w);
        Ws[r0][c4+0]=f2tf32(pw0.x); Ws[r0][c4+1]=f2tf32(pw0.y); Ws[r0][c4+2]=f2tf32(pw0.z); Ws[r0][c4+3]=f2tf32(pw0.w);
        Ws[r1][c4+0]=f2tf32(pw1.x); Ws[r1][c4+1]=f2tf32(pw1.y); Ws[r1][c4+2]=f2tf32(pw1.z); Ws[r1][c4+3]=f2tf32(pw1.w);
    }
    __syncthreads();

    for (int kb = GBK; kb <= K; kb += GBK) {
        const bool has_next = (kb < K);
        if (has_next) {
            pa0 = *(const float4*)&A[(size_t)(bm + r0) * K + kb + c4];
            pa1 = *(const float4*)&A[(size_t)(bm + r1) * K + kb + c4];
            pw0 = *(const float4*)&W[(size_t)(bn + r0) * K + kb + c4];
            pw1 = *(const float4*)&W[(size_t)(bn + r1) * K + kb + c4];
        }

        #pragma unroll
        for (int ks = 0; ks < 2; ks++) {
            uint32_t af[4][4], bf[4][2];
            const int kc = ks * 8 + gc;
            #pragma unroll
            for (int mf = 0; mf < 4; mf++) {
                const int r = wm * 64 + mf * 16 + gr;
                af[mf][0] = As[r    ][kc    ];
                af[mf][1] = As[r + 8][kc    ];
                af[mf][2] = As[r    ][kc + 4];
                af[mf][3] = As[r + 8][kc + 4];
            }
            #pragma unroll
            for (int nf = 0; nf < 4; nf++) {
                const int n = wn * 32 + nf * 8 + gr;
                bf[nf][0] = Ws[n][kc    ];
                bf[nf][1] = Ws[n][kc + 4];
            }
            #pragma unroll
            for (int mf = 0; mf < 4; mf++)
                #pragma unroll
                for (int nf = 0; nf < 4; nf++)
                    mma_tf32(acc[mf][nf], af[mf], bf[nf]);
        }
        __syncthreads();

        if (has_next) {
            As[r0][c4+0]=f2tf32(pa0.x); As[r0][c4+1]=f2tf32(pa0.y); As[r0][c4+2]=f2tf32(pa0.z); As[r0][c4+3]=f2tf32(pa0.w);
            As[r1][c4+0]=f2tf32(pa1.x); As[r1][c4+1]=f2tf32(pa1.y); As[r1][c4+2]=f2tf32(pa1.z); As[r1][c4+3]=f2tf32(pa1.w);
            Ws[r0][c4+0]=f2tf32(pw0.x); Ws[r0][c4+1]=f2tf32(pw0.y); Ws[r0][c4+2]=f2tf32(pw0.z); Ws[r0][c4+3]=f2tf32(pw0.w);
            Ws[r1][c4+0]=f2tf32(pw1.x); Ws[r1][c4+1]=f2tf32(pw1.y); Ws[r1][c4+2]=f2tf32(pw1.z); Ws[r1][c4+3]=f2tf32(pw1.w);
            __syncthreads();
        }
    }

    // epilogue: each (mf,nf) frag: rows m0, m0+8; cols n0, n0+1
    #pragma unroll
    for (int mf = 0; mf < 4; mf++) {
        #pragma unroll
        for (int nf = 0; nf < 4; nf++) {
            const int m0 = bm + wm * 64 + mf * 16 + gr;
            const int n0 = bn + wn * 32 + nf * 8 + 2 * gc;
            #pragma unroll
            for (int half = 0; half < 2; half++) {
                const int m = m0 + half * 8;
                float v0 = acc[mf][nf][half * 2 + 0] + bias[n0];
                float v1 = acc[mf][nf][half * 2 + 1] + bias[n0 + 1];
                if (EPI == 1) {
                    v0 += R[(size_t)m * N + n0];
                    v1 += R[(size_t)m * N + n0 + 1];
                }
                if (EPI == 2) {
                    v0 = 0.5f * v0 * (1.0f + erff(v0 * 0.70710678118654752f));
                    v1 = 0.5f * v1 * (1.0f + erff(v1 * 0.70710678118654752f));
                }
                if (EPI == 3) {
                    v0 *= R[(size_t)m * N + n0];
                    v1 *= R[(size_t)m * N + n0 + 1];
                }
                *(float2*)&C[(size_t)m * N + n0] = make_float2(v0, v1);
            }
        }
    }
}

// ---------------- RoPE (interleaved pairs, theta=10000), in-place -----------
__global__ void rope_kernel(float* __restrict__ X)
{
    int idx = blockIdx.x * blockDim.x + threadIdx.x;   // over Mz*Ez/2 pairs
    if (idx >= Mz * Ez / 2) return;
    int row = idx / (Ez / 2);
    int p   = idx % (Ez / 2);
    int s   = row % Ssz;
    int d2  = p % (Dd / 2);                            // pair index 0..31
    int h   = p / (Dd / 2);
    float inv = powf(10000.0f, -(float)(2 * d2) / (float)Dd);
    float fr  = (float)s * inv;
    float c = cosf(fr), sn = sinf(fr);
    float* x = X + (size_t)row * Ez + h * Dd + d2 * 2;
    float x0 = x[0], x1 = x[1];
    x[0] = x0 * c - x1 * sn;
    x[1] = x1 * c + x0 * sn;
}

// ---------------- sparse attention: block per (b,h,q) -----------------------
__global__ void attn_kernel(const float* __restrict__ Q, const float* __restrict__ K,
                            const float* __restrict__ V, const float* __restrict__ rpb,
                            const float* __restrict__ pc, float* __restrict__ ctx)
{
    __shared__ float sc[Ssz];
    __shared__ float qs[Dd];
    __shared__ float red[128];

    const int q = blockIdx.x, h = blockIdx.y, b = blockIdx.z;
    const int t = threadIdx.x;                         // 128 threads

    const float* qrow = Q + ((size_t)(b * Ssz + q)) * Ez + h * Dd;
    if (t < Dd) qs[t] = qrow[t];

    int lo = q - WIN; if (lo < 0) lo = 0;
    int hi = q + WIN; if (hi > Ssz - 1) hi = Ssz - 1;
    int extra = 0, nk;
    if (q == 0) { nk = Ssz; }
    else { extra = (lo > 0) ? 1 : 0; nk = hi - lo + 1 + extra; }
    __syncthreads();

    const float pch = pc[h];
    const float* rb = rpb + ((size_t)b * Ssz + q) * Ssz;

    for (int i = t; i < nk; i += 128) {
        int k = (q == 0) ? i : ((extra && i == 0) ? 0 : lo + i - extra);
        const float* kr = K + ((size_t)(b * Ssz + k)) * Ez + h * Dd;
        float s = 0.0f;
        #pragma unroll
        for (int d = 0; d < Dd; d++) s += qs[d] * kr[d];
        sc[i] = s * 0.125f + pch * rb[k];
    }
    __syncthreads();

    // block max
    float mx = -1e30f;
    for (int i = t; i < nk; i += 128) mx = fmaxf(mx, sc[i]);
    red[t] = mx; __syncthreads();
    for (int o = 64; o > 0; o >>= 1) { if (t < o) red[t] = fmaxf(red[t], red[t + o]); __syncthreads(); }
    mx = red[0]; __syncthreads();

    // exp + sum
    float sm = 0.0f;
    for (int i = t; i < nk; i += 128) { float e = expf(sc[i] - mx); sc[i] = e; sm += e; }
    red[t] = sm; __syncthreads();
    for (int o = 64; o > 0; o >>= 1) { if (t < o) red[t] += red[t + o]; __syncthreads(); }
    const float inv = 1.0f / red[0];
    __syncthreads();

    // ctx: 2 partial accumulators per d
    const int d = t & 63, half = t >> 6;
    float acc = 0.0f;
    for (int i = half; i < nk; i += 2) {
        int k = (q == 0) ? i : ((extra && i == 0) ? 0 : lo + i - extra);
        acc += sc[i] * V[((size_t)(b * Ssz + k)) * Ez + h * Dd + d];
    }
    red[t] = acc; __syncthreads();
    if (t < 64)
        ctx[((size_t)(b * Ssz + q)) * Ez + h * Dd + t] = (red[t] + red[t + 64]) * inv;
}

// ---------------- LayerNorm: block per row ----------------------------------
__global__ void layernorm_kernel(const float* __restrict__ X, const float* __restrict__ sc,
                                 const float* __restrict__ bi, float* __restrict__ out)
{
    __shared__ float b1[256], b2[256];
    const int row = blockIdx.x;
    const int t = threadIdx.x;                         // 256
    const float* x = X + (size_t)row * Ez;
    float sm = 0.0f, sq = 0.0f;
    for (int i = t; i < Ez; i += 256) { float v = x[i]; sm += v; sq += v * v; }
    b1[t] = sm; b2[t] = sq; __syncthreads();
    for (int o = 128; o > 0; o >>= 1) {
        if (t < o) { b1[t] += b1[t + o]; b2[t] += b2[t + o]; }
        __syncthreads();
    }
    const float mean = b1[0] * (1.0f / Ez);
    const float var  = b2[0] * (1.0f / Ez) - mean * mean;
    const float rstd = rsqrtf(var + 1e-5f);
    float* o = out + (size_t)row * Ez;
    for (int i = t; i < Ez; i += 256)
        o[i] = (x[i] - mean) * rstd * sc[i] + bi[i];
}

// ---------------- launch -----------------------------------------------------
extern "C" void kernel_launch(void* const* d_in, const int* in_sizes, int n_in,
                              void* d_out, int out_size)
{
    const float* x      = (const float*)d_in[0];
    const float* rpb    = (const float*)d_in[1];
    // d_in[2]: mask — all-True by construction, pattern handled analytically
    const float* wq_w   = (const float*)d_in[3];
    const float* wq_b   = (const float*)d_in[4];
    const float* wk_w   = (const float*)d_in[5];
    const float* wk_b   = (const float*)d_in[6];
    const float* wv_w   = (const float*)d_in[7];
    const float* wv_b   = (const float*)d_in[8];
    const float* fc_w   = (const float*)d_in[9];
    const float* fc_b   = (const float*)d_in[10];
    const float* pos    = (const float*)d_in[11];
    const float* gate_w = (const float*)d_in[12];
    const float* gate_b = (const float*)d_in[13];
    const float* val_w  = (const float*)d_in[14];
    const float* val_b  = (const float*)d_in[15];
    const float* down_w = (const float*)d_in[16];
    const float* down_b = (const float*)d_in[17];
    const float* ln1_s  = (const float*)d_in[18];
    const float* ln1_b  = (const float*)d_in[19];
    const float* ln2_s  = (const float*)d_in[20];
    const float* ln2_b  = (const float*)d_in[21];
    float* out = (float*)d_out;

    float *Q, *K, *V, *ctx, *t1, *h, *gate;
    cudaGetSymbolAddress((void**)&Q,   g_Q);
    cudaGetSymbolAddress((void**)&K,   g_K);
    cudaGetSymbolAddress((void**)&V,   g_V);
    cudaGetSymbolAddress((void**)&ctx, g_ctx);
    cudaGetSymbolAddress((void**)&t1,  g_t1);
    cudaGetSymbolAddress((void**)&h,   g_h);
    cudaGetSymbolAddress((void**)&gate, g_gate);

    dim3 gE(Ez / 128, Mz / 128);        // (6, 32)
    dim3 gF(FFN / 128, Mz / 128);       // (24, 32)

    // QKV projections
    gemm_tf32<0><<<gE, 256>>>(x, wq_w, wq_b, nullptr, Q, Mz, Ez, Ez);
    gemm_tf32<0><<<gE, 256>>>(x, wk_w, wk_b, nullptr, K, Mz, Ez, Ez);
    gemm_tf32<0><<<gE, 256>>>(x, wv_w, wv_b, nullptr, V, Mz, Ez, Ez);

    // RoPE on Q, K
    int npair = Mz * Ez / 2;
    rope_kernel<<<(npair + 255) / 256, 256>>>(Q);
    rope_kernel<<<(npair + 255) / 256, 256>>>(K);

    // sparse attention
    attn_kernel<<<dim3(Ssz, Hh, Bz), 128>>>(Q, K, V, rpb, pos, ctx);

    // fc + residual, LN1
    gemm_tf32<1><<<gE, 256>>>(ctx, fc_w, fc_b, x, t1, Mz, Ez, Ez);
    layernorm_kernel<<<Mz, 256>>>(t1, ln1_s, ln1_b, h);

    // GeGLU FFN: gate (gelu), value (* gate), down (+h), LN2
    gemm_tf32<2><<<gF, 256>>>(h, gate_w, gate_b, nullptr, gate, Mz, FFN, Ez);
    gemm_tf32<3><<<gF, 256>>>(h, val_w,  val_b,  gate,    gate, Mz, FFN, Ez);
    gemm_tf32<1><<<gE, 256>>>(gate, down_w, down_b, h, t1, Mz, Ez, FFN);
    layernorm_kernel<<<Mz, 256>>>(t1, ln2_s, ln2_b, out);
}